// round 1
// baseline (speedup 1.0000x reference)
#include <cuda_runtime.h>
#include <cuda_bf16.h>

// CoherenceGate: out = sigmoid( psi_re * (psi_re @ W^T) + psi_im * (psi_im @ W^T) + bias )
// B = 8192, K = 1024 (derived from in_sizes at launch).
//
// Fused dual-GEMM: both GEMMs (re and im) share the same W tile in shared memory.
// CTA tile: BM=64 rows (batch) x BN=128 cols (output k), BK=32 reduction slice.
// Thread micro-tile: 4x8 for re AND im (64 fp32 accumulators).

#define BM 64
#define BN 128
#define BK 32
#define TM 4
#define TN 8

// padded leading dims (floats). Both row strides are multiples of 4 floats
// so float4 (16B) accesses stay aligned.
#define LDA (BM + 4)   // 68
#define LDW (BN + 4)   // 132

__global__ __launch_bounds__(256, 2)
void coherence_gate_kernel(const float* __restrict__ pre,
                           const float* __restrict__ pim,
                           const float* __restrict__ W,
                           const float* __restrict__ bias,
                           float* __restrict__ out,
                           int Kdim)
{
    __shared__ __align__(16) float sAre[BK][LDA];
    __shared__ __align__(16) float sAim[BK][LDA];
    __shared__ __align__(16) float sW  [BK][LDW];

    const int tid = threadIdx.x;     // 0..255
    const int tx  = tid & 15;        // output-column group (16 groups)
    const int ty  = tid >> 4;        // output-row group    (16 groups)

    const int block_k = blockIdx.x * BN;   // output-column tile origin
    const int block_b = blockIdx.y * BM;   // batch-row tile origin

    float acc_re[TM][TN];
    float acc_im[TM][TN];
#pragma unroll
    for (int m = 0; m < TM; ++m)
#pragma unroll
        for (int n = 0; n < TN; ++n) { acc_re[m][n] = 0.f; acc_im[m][n] = 0.f; }

    const size_t ldg = (size_t)Kdim;   // row stride of psi / W (1024)

    for (int j0 = 0; j0 < Kdim; j0 += BK) {
        // ---- load A_re / A_im tiles: 64 rows x 32 cols = 512 float4, 2/thread ----
#pragma unroll
        for (int t = 0; t < 2; ++t) {
            int idx = tid + t * 256;
            int r   = idx >> 3;          // row within tile (0..63)
            int jv  = idx & 7;           // float4 index within row (0..7)
            const float4 vre = *(const float4*)&pre[(size_t)(block_b + r) * ldg + j0 + jv * 4];
            const float4 vim = *(const float4*)&pim[(size_t)(block_b + r) * ldg + j0 + jv * 4];
            sAre[jv * 4 + 0][r] = vre.x;
            sAre[jv * 4 + 1][r] = vre.y;
            sAre[jv * 4 + 2][r] = vre.z;
            sAre[jv * 4 + 3][r] = vre.w;
            sAim[jv * 4 + 0][r] = vim.x;
            sAim[jv * 4 + 1][r] = vim.y;
            sAim[jv * 4 + 2][r] = vim.z;
            sAim[jv * 4 + 3][r] = vim.w;
        }
        // ---- load W tile: 128 rows(k) x 32 cols(j) = 1024 float4, 4/thread ----
#pragma unroll
        for (int t = 0; t < 4; ++t) {
            int idx = tid + t * 256;
            int r   = idx >> 3;          // k within tile (0..127)
            int jv  = idx & 7;
            const float4 v = *(const float4*)&W[(size_t)(block_k + r) * ldg + j0 + jv * 4];
            sW[jv * 4 + 0][r] = v.x;
            sW[jv * 4 + 1][r] = v.y;
            sW[jv * 4 + 2][r] = v.z;
            sW[jv * 4 + 3][r] = v.w;
        }
        __syncthreads();

        // ---- compute: 32 j-steps, 64 FMAs each ----
#pragma unroll
        for (int j = 0; j < BK; ++j) {
            const float4 ar = *(const float4*)&sAre[j][ty * 4];
            const float4 ai = *(const float4*)&sAim[j][ty * 4];
            const float4 w0 = *(const float4*)&sW[j][tx * 4];
            const float4 w1 = *(const float4*)&sW[j][64 + tx * 4];

            const float a_re[TM] = {ar.x, ar.y, ar.z, ar.w};
            const float a_im[TM] = {ai.x, ai.y, ai.z, ai.w};
            const float w[TN]    = {w0.x, w0.y, w0.z, w0.w, w1.x, w1.y, w1.z, w1.w};

#pragma unroll
            for (int m = 0; m < TM; ++m) {
#pragma unroll
                for (int n = 0; n < TN; ++n) {
                    acc_re[m][n] = fmaf(a_re[m], w[n], acc_re[m][n]);
                    acc_im[m][n] = fmaf(a_im[m], w[n], acc_im[m][n]);
                }
            }
        }
        __syncthreads();
    }

    // ---- epilogue: logits = psi_re*u_re + psi_im*u_im + bias; out = sigmoid ----
#pragma unroll
    for (int m = 0; m < TM; ++m) {
        const int b = block_b + ty * 4 + m;
#pragma unroll
        for (int n = 0; n < TN; ++n) {
            const int k = block_k + ((n < 4) ? (tx * 4 + n) : (64 + tx * 4 + (n - 4)));
            const float xre = pre[(size_t)b * ldg + k];
            const float xim = pim[(size_t)b * ldg + k];
            const float logit = fmaf(xre, acc_re[m][n], fmaf(xim, acc_im[m][n], bias[k]));
            out[(size_t)b * ldg + k] = 1.0f / (1.0f + __expf(-logit));
        }
    }
}

extern "C" void kernel_launch(void* const* d_in, const int* in_sizes, int n_in,
                              void* d_out, int out_size)
{
    const float* pre  = (const float*)d_in[0];  // psi_re (B*K)
    const float* pim  = (const float*)d_in[1];  // psi_im (B*K)
    const float* W    = (const float*)d_in[2];  // W (K*K)
    const float* bias = (const float*)d_in[3];  // bias (K)
    float* out = (float*)d_out;

    const int K = in_sizes[3];            // 1024
    const int B = in_sizes[0] / K;        // 8192

    dim3 grid(K / BN, B / BM);            // (8, 128)
    dim3 block(256);
    coherence_gate_kernel<<<grid, block>>>(pre, pim, W, bias, out, K);
}

// round 3
// speedup vs baseline: 2.5355x; 2.5355x over previous
#include <cuda_runtime.h>
#include <cuda_bf16.h>
#include <cstdint>

// CoherenceGate via mma.sync.m16n8k8.tf32 (sm_100 baseline ISA — tcgen05 is
// unavailable: harness compiles PTX with .target sm_100, no 'a' suffix).
//
// out = sigmoid( psi_re*(psi_re@W^T) + psi_im*(psi_im@W^T) + bias )
// B=8192, K=1024.
// CTA tile 128(b) x 128(k_out), BK=32. 8 warps (4x2), warp tile 32x64 per GEMM.
// Both GEMMs share all A-row addressing and all W fragments.

#define KDIM 1024
#define BMT 128
#define BNT 128
#define BK  32

#define ROW_F   36              // floats per smem row (32 + 4 pad) -> conflict-free
#define TILE_F  (128 * ROW_F)   // 4608 floats per tile
#define AIM_F   TILE_F          // offsets within a stage (in floats)
#define W_F     (2 * TILE_F)
#define STAGE_F (3 * TILE_F)    // 13824 floats = 55296 B
#define SMEM_BYTES (2 * STAGE_F * 4)   // 110592 B

__device__ __forceinline__ uint32_t smem_u32(const void* p) {
    uint32_t a;
    asm("{ .reg .u64 t; cvta.to.shared.u64 t, %1; cvt.u32.u64 %0, t; }" : "=r"(a) : "l"(p));
    return a;
}
__device__ __forceinline__ void cp16(uint32_t dst, const void* src) {
    asm volatile("cp.async.cg.shared.global [%0], [%1], 16;" :: "r"(dst), "l"(src) : "memory");
}
__device__ __forceinline__ uint32_t f2tf(float x) {
    uint32_t r;
    asm("cvt.rna.tf32.f32 %0, %1;" : "=r"(r) : "f"(x));
    return r;
}
__device__ __forceinline__ void mma8(float* d, const uint32_t* a, const uint32_t* b) {
    asm volatile(
        "mma.sync.aligned.m16n8k8.row.col.f32.tf32.tf32.f32 "
        "{%0,%1,%2,%3},{%4,%5,%6,%7},{%8,%9},{%0,%1,%2,%3};"
        : "+f"(d[0]), "+f"(d[1]), "+f"(d[2]), "+f"(d[3])
        : "r"(a[0]), "r"(a[1]), "r"(a[2]), "r"(a[3]), "r"(b[0]), "r"(b[1]));
}
__device__ __forceinline__ float sigf(float x) {
    return __fdividef(1.0f, 1.0f + __expf(-x));
}

// load one BK-slice stage: A_re, A_im (128x32) + W (128x32), 16B per cp.async
__device__ __forceinline__ void load_stage(const float* __restrict__ pre,
                                           const float* __restrict__ pim,
                                           const float* __restrict__ Wm,
                                           uint32_t sbase, int buf, int j0,
                                           int block_b, int block_k, int tid)
{
    const uint32_t sb = sbase + (uint32_t)buf * (STAGE_F * 4);
#pragma unroll
    for (int t = 0; t < 4; ++t) {
        const int c   = tid + t * 256;      // 0..1023
        const int row = c >> 3;
        const int ch  = c & 7;
        const uint32_t so = (uint32_t)(row * (ROW_F * 4) + ch * 16);
        const size_t ga = (size_t)(block_b + row) * KDIM + j0 + ch * 4;
        cp16(sb + so,               pre + ga);
        cp16(sb + AIM_F * 4 + so,   pim + ga);
        cp16(sb + W_F * 4 + so,     Wm + (size_t)(block_k + row) * KDIM + j0 + ch * 4);
    }
}

__global__ __launch_bounds__(256, 1)
void coherence_gate_mma(const float* __restrict__ pre,
                        const float* __restrict__ pim,
                        const float* __restrict__ Wm,
                        const float* __restrict__ bias,
                        float* __restrict__ out)
{
    extern __shared__ __align__(16) float smem[];
    const uint32_t sbase = smem_u32(smem);

    const int tid    = threadIdx.x;
    const int wid    = tid >> 5;
    const int lane   = tid & 31;
    const int g      = lane >> 2;   // group id (0..7)
    const int tg     = lane & 3;    // thread in group (0..3)
    const int warp_m = wid & 3;     // 0..3  -> 32-row band
    const int warp_n = wid >> 2;    // 0..1  -> 64-col band

    const int block_k = blockIdx.x * BNT;
    const int block_b = blockIdx.y * BMT;

    float dre[2][8][4], dim_[2][8][4];
#pragma unroll
    for (int mt = 0; mt < 2; ++mt)
#pragma unroll
        for (int nt = 0; nt < 8; ++nt)
#pragma unroll
            for (int q = 0; q < 4; ++q) { dre[mt][nt][q] = 0.f; dim_[mt][nt][q] = 0.f; }

    // prologue: 2 stages
    load_stage(pre, pim, Wm, sbase, 0, 0,  block_b, block_k, tid);
    asm volatile("cp.async.commit_group;" ::: "memory");
    load_stage(pre, pim, Wm, sbase, 1, BK, block_b, block_k, tid);
    asm volatile("cp.async.commit_group;" ::: "memory");

    const int NS = KDIM / BK;   // 32
    for (int s = 0; s < NS; ++s) {
        asm volatile("cp.async.wait_group 1;" ::: "memory");
        __syncthreads();

        const float* bs = smem + (s & 1) * STAGE_F;

#pragma unroll
        for (int ks = 0; ks < 4; ++ks) {
            const int jb = ks * 8;

            uint32_t areF[2][4], aimF[2][4];
#pragma unroll
            for (int mt = 0; mt < 2; ++mt) {
                const int r0 = warp_m * 32 + mt * 16 + g;
                const float* pr = bs + r0 * ROW_F + jb;
                areF[mt][0] = f2tf(pr[tg]);
                areF[mt][1] = f2tf(pr[8 * ROW_F + tg]);
                areF[mt][2] = f2tf(pr[tg + 4]);
                areF[mt][3] = f2tf(pr[8 * ROW_F + tg + 4]);
                const float* pi = bs + AIM_F + r0 * ROW_F + jb;
                aimF[mt][0] = f2tf(pi[tg]);
                aimF[mt][1] = f2tf(pi[8 * ROW_F + tg]);
                aimF[mt][2] = f2tf(pi[tg + 4]);
                aimF[mt][3] = f2tf(pi[8 * ROW_F + tg + 4]);
            }
            uint32_t bF[8][2];
#pragma unroll
            for (int nt = 0; nt < 8; ++nt) {
                const float* pw = bs + W_F + (warp_n * 64 + nt * 8 + g) * ROW_F + jb;
                bF[nt][0] = f2tf(pw[tg]);
                bF[nt][1] = f2tf(pw[tg + 4]);
            }
#pragma unroll
            for (int mt = 0; mt < 2; ++mt)
#pragma unroll
                for (int nt = 0; nt < 8; ++nt) {
                    mma8(dre[mt][nt],  areF[mt], bF[nt]);
                    mma8(dim_[mt][nt], aimF[mt], bF[nt]);
                }
        }

        __syncthreads();
        const int ls = s + 2;
        if (ls < NS)
            load_stage(pre, pim, Wm, sbase, s & 1, ls * BK, block_b, block_k, tid);
        asm volatile("cp.async.commit_group;" ::: "memory");
    }

    // ---- epilogue: fully register-resident ----
#pragma unroll
    for (int mt = 0; mt < 2; ++mt) {
#pragma unroll
        for (int rr = 0; rr < 2; ++rr) {            // row g / g+8  -> frag regs {0,1}/{2,3}? no: {0,1}=(g,g+8)? 
            // fragment mapping: d0=(g,2tg), d1=(g,2tg+1), d2=(g+8,2tg), d3=(g+8,2tg+1)
            const int row = block_b + warp_m * 32 + mt * 16 + g + rr * 8;
            const size_t brow = (size_t)row * KDIM;
#pragma unroll
            for (int nt = 0; nt < 8; ++nt) {
                const int k = block_k + warp_n * 64 + nt * 8 + 2 * tg;
                const float2 xr = *(const float2*)&pre[brow + k];
                const float2 xi = *(const float2*)&pim[brow + k];
                const float2 bv = *(const float2*)&bias[k];
                const float ur0 = dre[mt][nt][rr * 2 + 0];
                const float ur1 = dre[mt][nt][rr * 2 + 1];
                const float ui0 = dim_[mt][nt][rr * 2 + 0];
                const float ui1 = dim_[mt][nt][rr * 2 + 1];
                float2 o;
                o.x = sigf(fmaf(xr.x, ur0, fmaf(xi.x, ui0, bv.x)));
                o.y = sigf(fmaf(xr.y, ur1, fmaf(xi.y, ui1, bv.y)));
                *(float2*)&out[brow + k] = o;
            }
        }
    }
}

extern "C" void kernel_launch(void* const* d_in, const int* in_sizes, int n_in,
                              void* d_out, int out_size)
{
    const float* pre  = (const float*)d_in[0];
    const float* pim  = (const float*)d_in[1];
    const float* Wm   = (const float*)d_in[2];
    const float* bias = (const float*)d_in[3];
    float* out = (float*)d_out;

    const int K = in_sizes[3];        // 1024
    const int B = in_sizes[0] / K;    // 8192

    cudaFuncSetAttribute(coherence_gate_mma,
                         cudaFuncAttributeMaxDynamicSharedMemorySize, SMEM_BYTES);

    dim3 grid(K / BNT, B / BMT);      // (8, 64) = 512 CTAs
    coherence_gate_mma<<<grid, 256, SMEM_BYTES>>>(pre, pim, Wm, bias, out);
}

// round 4
// speedup vs baseline: 5.3011x; 2.0907x over previous
#include <cuda_runtime.h>
#include <cuda_fp16.h>
#include <cstdint>

// CoherenceGate via fp16 mma.sync.m16n8k16 (sm_100 baseline ISA).
// out = sigmoid( psi_re*(psi_re@W^T) + psi_im*(psi_im@W^T) + bias )
// B=8192, K=1024.
//
// Phase 1: convert psi_re/psi_im/W (fp32) -> fp16 scratch (W scaled by 256).
// Phase 2: dual-GEMM, CTA 128x128, BK=32, 512 threads (16 warps, 4x4),
//          warp tile 32x32 per GEMM, ldmatrix.x4 + m16n8k16, 3-stage cp.async.
// Epilogue reads original fp32 psi/bias for the elementwise part.

#define KDIM 1024
#define BDIM 8192
#define BM 128
#define BN 128
#define BK 32
#define NTHREADS 512
#define PIPE 3

#define W_SCALE 256.0f
#define W_INV   (1.0f / 256.0f)

// smem (halfs): each tile 128 rows x 32 cols, 64 B/row -> 8192 B
#define TILE_BYTES 8192
#define OFF_ARE 0
#define OFF_AIM 8192
#define OFF_W   16384
#define STAGE_BYTES 24576
#define SMEM_BYTES (PIPE * STAGE_BYTES)   // 73728

// fp16 scratch (static device globals — not an allocation)
__device__ __half g_pre16[(size_t)BDIM * KDIM];
__device__ __half g_pim16[(size_t)BDIM * KDIM];
__device__ __half g_W16[(size_t)KDIM * KDIM];

__device__ __forceinline__ uint32_t smem_u32(const void* p) {
    uint32_t a;
    asm("{ .reg .u64 t; cvta.to.shared.u64 t, %1; cvt.u32.u64 %0, t; }" : "=r"(a) : "l"(p));
    return a;
}
__device__ __forceinline__ void cp16(uint32_t dst, const void* src) {
    asm volatile("cp.async.cg.shared.global [%0], [%1], 16;" :: "r"(dst), "l"(src) : "memory");
}
__device__ __forceinline__ void ldsm4(uint32_t* r, uint32_t addr) {
    asm volatile("ldmatrix.sync.aligned.m8n8.x4.shared.b16 {%0,%1,%2,%3}, [%4];"
                 : "=r"(r[0]), "=r"(r[1]), "=r"(r[2]), "=r"(r[3]) : "r"(addr));
}
__device__ __forceinline__ void mma16(float* d, const uint32_t* a, const uint32_t* b) {
    asm volatile(
        "mma.sync.aligned.m16n8k16.row.col.f32.f16.f16.f32 "
        "{%0,%1,%2,%3},{%4,%5,%6,%7},{%8,%9},{%0,%1,%2,%3};"
        : "+f"(d[0]), "+f"(d[1]), "+f"(d[2]), "+f"(d[3])
        : "r"(a[0]), "r"(a[1]), "r"(a[2]), "r"(a[3]), "r"(b[0]), "r"(b[1]));
}
__device__ __forceinline__ float sigf(float x) {
    return __fdividef(1.0f, 1.0f + __expf(-x));
}

// ---------------- phase 1: fp32 -> fp16 convert ----------------
__global__ void cvt16_kernel(const float4* __restrict__ src, int n4, float scale, int which)
{
    __half* dstb = (which == 0) ? g_pre16 : (which == 1) ? g_pim16 : g_W16;
    uint2* dst = reinterpret_cast<uint2*>(dstb);
    const int stride = gridDim.x * blockDim.x;
    for (int i = blockIdx.x * blockDim.x + threadIdx.x; i < n4; i += stride) {
        const float4 v = src[i];
        const __half2 h0 = __floats2half2_rn(v.x * scale, v.y * scale);
        const __half2 h1 = __floats2half2_rn(v.z * scale, v.w * scale);
        uint2 o;
        o.x = *(const uint32_t*)&h0;
        o.y = *(const uint32_t*)&h1;
        dst[i] = o;
    }
}

// swizzled smem byte offset for (row, 16B-chunk c in 0..3), 64B rows
__device__ __forceinline__ uint32_t swoff(int row, int ch) {
    return (uint32_t)(row * 64 + ((ch ^ ((row >> 1) & 3)) * 16));
}

__device__ __forceinline__ void load_stage(uint32_t sbase, int buf, int j0,
                                           int block_b, int block_k, int tid)
{
    const uint32_t sb = sbase + (uint32_t)buf * STAGE_BYTES;
    const int row = tid >> 2;      // 0..127
    const int ch  = tid & 3;       // 0..3
    const uint32_t so = swoff(row, ch);
    const size_t ga = (size_t)(block_b + row) * KDIM + j0 + ch * 8;
    cp16(sb + OFF_ARE + so, g_pre16 + ga);
    cp16(sb + OFF_AIM + so, g_pim16 + ga);
    cp16(sb + OFF_W + so, g_W16 + (size_t)(block_k + row) * KDIM + j0 + ch * 8);
}

// ---------------- phase 2: dual-GEMM + fused sigmoid ----------------
__global__ __launch_bounds__(NTHREADS, 1)
void coherence_gate_h(const float* __restrict__ pre,
                      const float* __restrict__ pim,
                      const float* __restrict__ bias,
                      float* __restrict__ out)
{
    extern __shared__ __align__(128) char smem[];
    const uint32_t sbase = smem_u32(smem);

    const int tid    = threadIdx.x;
    const int wid    = tid >> 5;
    const int lane   = tid & 31;
    const int g      = lane >> 2;
    const int tg     = lane & 3;
    const int warp_m = wid & 3;    // 0..3 -> 32-row band
    const int warp_n = wid >> 2;   // 0..3 -> 32-col band

    const int block_k = blockIdx.x * BN;
    const int block_b = blockIdx.y * BM;

    float dre[2][4][4], dim_[2][4][4];
#pragma unroll
    for (int mt = 0; mt < 2; ++mt)
#pragma unroll
        for (int nt = 0; nt < 4; ++nt)
#pragma unroll
            for (int q = 0; q < 4; ++q) { dre[mt][nt][q] = 0.f; dim_[mt][nt][q] = 0.f; }

    // per-thread ldmatrix address components
    // A (re/im): lane L -> row = warp_m*32 + mt*16 + (L&15), chunk hi-bit = L>>4
    const int a_rl   = lane & 15;
    const int a_chi  = lane >> 4;          // 0/1
    // W: lane L -> M = L>>3, r = L&7
    const int w_M    = lane >> 3;          // 0..3
    const int w_r    = lane & 7;
    const int w_kc   = w_M & 1;            // k-chunk select
    const int w_nadd = (w_M >> 1) * 8;     // n sub-block

    int arow[2], aswz[2];
#pragma unroll
    for (int mt = 0; mt < 2; ++mt) {
        arow[mt] = warp_m * 32 + mt * 16 + a_rl;
        aswz[mt] = (arow[mt] >> 1) & 3;
    }
    int wrow[2], wswz[2];
#pragma unroll
    for (int ntp = 0; ntp < 2; ++ntp) {
        wrow[ntp] = warp_n * 32 + ntp * 16 + w_nadd + w_r;
        wswz[ntp] = (wrow[ntp] >> 1) & 3;
    }

    // prologue
#pragma unroll
    for (int s = 0; s < PIPE; ++s) {
        load_stage(sbase, s, s * BK, block_b, block_k, tid);
        asm volatile("cp.async.commit_group;" ::: "memory");
    }

    const int NS = KDIM / BK;   // 32
    for (int s = 0; s < NS; ++s) {
        asm volatile("cp.async.wait_group %0;" :: "n"(PIPE - 1) : "memory");
        __syncthreads();

        const uint32_t sb = sbase + (uint32_t)(s % PIPE) * STAGE_BYTES;

#pragma unroll
        for (int ks = 0; ks < 2; ++ks) {
            uint32_t ar[2][4], ai[2][4], bw[2][4];
#pragma unroll
            for (int mt = 0; mt < 2; ++mt) {
                const uint32_t ao = (uint32_t)(arow[mt] * 64 +
                                    (((2 * ks + a_chi) ^ aswz[mt]) * 16));
                ldsm4(ar[mt], sb + OFF_ARE + ao);
                ldsm4(ai[mt], sb + OFF_AIM + ao);
            }
#pragma unroll
            for (int ntp = 0; ntp < 2; ++ntp) {
                const uint32_t wo = (uint32_t)(wrow[ntp] * 64 +
                                    (((2 * ks + w_kc) ^ wswz[ntp]) * 16));
                ldsm4(bw[ntp], sb + OFF_W + wo);
            }
#pragma unroll
            for (int mt = 0; mt < 2; ++mt)
#pragma unroll
                for (int nt = 0; nt < 4; ++nt) {
                    mma16(dre[mt][nt],  ar[mt], &bw[nt >> 1][(nt & 1) * 2]);
                    mma16(dim_[mt][nt], ai[mt], &bw[nt >> 1][(nt & 1) * 2]);
                }
        }

        __syncthreads();
        const int ls = s + PIPE;
        if (ls < NS)
            load_stage(sbase, s % PIPE, ls * BK, block_b, block_k, tid);
        asm volatile("cp.async.commit_group;" ::: "memory");
    }

    // ---- epilogue (register-resident; undo W_SCALE) ----
#pragma unroll
    for (int mt = 0; mt < 2; ++mt) {
#pragma unroll
        for (int rr = 0; rr < 2; ++rr) {
            const int row = block_b + warp_m * 32 + mt * 16 + g + rr * 8;
            const size_t brow = (size_t)row * KDIM;
#pragma unroll
            for (int nt = 0; nt < 4; ++nt) {
                const int k = block_k + warp_n * 32 + nt * 8 + 2 * tg;
                const float2 xr = *(const float2*)&pre[brow + k];
                const float2 xi = *(const float2*)&pim[brow + k];
                const float2 bv = *(const float2*)&bias[k];
                const float ur0 = dre[mt][nt][rr * 2 + 0] * W_INV;
                const float ur1 = dre[mt][nt][rr * 2 + 1] * W_INV;
                const float ui0 = dim_[mt][nt][rr * 2 + 0] * W_INV;
                const float ui1 = dim_[mt][nt][rr * 2 + 1] * W_INV;
                float2 o;
                o.x = sigf(fmaf(xr.x, ur0, fmaf(xi.x, ui0, bv.x)));
                o.y = sigf(fmaf(xr.y, ur1, fmaf(xi.y, ui1, bv.y)));
                *(float2*)&out[brow + k] = o;
            }
        }
    }
}

extern "C" void kernel_launch(void* const* d_in, const int* in_sizes, int n_in,
                              void* d_out, int out_size)
{
    const float* pre  = (const float*)d_in[0];
    const float* pim  = (const float*)d_in[1];
    const float* Wm   = (const float*)d_in[2];
    const float* bias = (const float*)d_in[3];
    float* out = (float*)d_out;

    const int K = in_sizes[3];        // 1024
    const int B = in_sizes[0] / K;    // 8192

    // phase 1: converts
    const int n4_psi = (B * K) / 4;
    const int n4_w   = (K * K) / 4;
    cvt16_kernel<<<1024, 256>>>((const float4*)pre, n4_psi, 1.0f, 0);
    cvt16_kernel<<<1024, 256>>>((const float4*)pim, n4_psi, 1.0f, 1);
    cvt16_kernel<<<256, 256>>>((const float4*)Wm, n4_w, W_SCALE, 2);

    // phase 2: GEMM
    cudaFuncSetAttribute(coherence_gate_h,
                         cudaFuncAttributeMaxDynamicSharedMemorySize, SMEM_BYTES);
    dim3 grid(K / BN, B / BM);        // (8, 64) = 512 CTAs
    coherence_gate_h<<<grid, NTHREADS, SMEM_BYTES>>>(pre, pim, bias, out);
}

// round 5
// speedup vs baseline: 6.4083x; 1.2089x over previous
#include <cuda_runtime.h>
#include <cuda_fp16.h>
#include <cstdint>

// CoherenceGate via fp16 mma.sync.m16n8k16 (sm_100 baseline ISA).
// out = sigmoid( psi_re*(psi_re@W^T) + psi_im*(psi_im@W^T) + bias )
// B=8192, K=1024.
//
// R5: 2 CTAs/SM (256 thr, tile 64x128), BK=64, single-barrier 3-stage pipeline.

#define KDIM 1024
#define BDIM 8192
#define BM 64
#define BN 128
#define BK 64
#define NTHREADS 256
#define PIPE 3
#define NS (KDIM / BK)      // 16

#define W_SCALE 256.0f
#define W_INV   (1.0f / 256.0f)

// smem halfs, 128B rows (64 halfs), swizzle: chunk ^ (row & 7)
#define OFF_ARE 0
#define OFF_AIM 8192          // A tiles: 64 rows x 128B = 8 KB each
#define OFF_W   16384         // W tile: 128 rows x 128B = 16 KB
#define STAGE_BYTES 32768
#define SMEM_BYTES (PIPE * STAGE_BYTES)   // 98304 per CTA

__device__ __half g_pre16[(size_t)BDIM * KDIM];
__device__ __half g_pim16[(size_t)BDIM * KDIM];
__device__ __half g_W16[(size_t)KDIM * KDIM];

__device__ __forceinline__ uint32_t smem_u32(const void* p) {
    uint32_t a;
    asm("{ .reg .u64 t; cvta.to.shared.u64 t, %1; cvt.u32.u64 %0, t; }" : "=r"(a) : "l"(p));
    return a;
}
__device__ __forceinline__ void cp16(uint32_t dst, const void* src) {
    asm volatile("cp.async.cg.shared.global [%0], [%1], 16;" :: "r"(dst), "l"(src) : "memory");
}
__device__ __forceinline__ void ldsm4(uint32_t* r, uint32_t addr) {
    asm volatile("ldmatrix.sync.aligned.m8n8.x4.shared.b16 {%0,%1,%2,%3}, [%4];"
                 : "=r"(r[0]), "=r"(r[1]), "=r"(r[2]), "=r"(r[3]) : "r"(addr));
}
__device__ __forceinline__ void mma16(float* d, const uint32_t* a, const uint32_t* b) {
    asm volatile(
        "mma.sync.aligned.m16n8k16.row.col.f32.f16.f16.f32 "
        "{%0,%1,%2,%3},{%4,%5,%6,%7},{%8,%9},{%0,%1,%2,%3};"
        : "+f"(d[0]), "+f"(d[1]), "+f"(d[2]), "+f"(d[3])
        : "r"(a[0]), "r"(a[1]), "r"(a[2]), "r"(a[3]), "r"(b[0]), "r"(b[1]));
}
__device__ __forceinline__ float sigf(float x) {
    return __fdividef(1.0f, 1.0f + __expf(-x));
}

// ---------------- phase 1: fp32 -> fp16 convert ----------------
__global__ void cvt16_kernel(const float4* __restrict__ src, int n4, float scale, int which)
{
    __half* dstb = (which == 0) ? g_pre16 : (which == 1) ? g_pim16 : g_W16;
    uint2* dst = reinterpret_cast<uint2*>(dstb);
    const int stride = gridDim.x * blockDim.x;
    for (int i = blockIdx.x * blockDim.x + threadIdx.x; i < n4; i += stride) {
        const float4 v = src[i];
        const __half2 h0 = __floats2half2_rn(v.x * scale, v.y * scale);
        const __half2 h1 = __floats2half2_rn(v.z * scale, v.w * scale);
        uint2 o;
        o.x = *(const uint32_t*)&h0;
        o.y = *(const uint32_t*)&h1;
        dst[i] = o;
    }
}

// ---------------- stage loader (8 cp.async / thread) ----------------
__device__ __forceinline__ void load_stage(uint32_t sbase, int buf, int j0,
                                           int block_b, int block_k, int tid)
{
    const uint32_t sb = sbase + (uint32_t)buf * STAGE_BYTES;
    // A tiles: 64 rows x 8 chunks = 512 chunks each -> 2/thread
#pragma unroll
    for (int t = 0; t < 2; ++t) {
        const int idx = tid + t * 256;
        const int row = idx >> 3;
        const int ch  = idx & 7;
        const uint32_t so = (uint32_t)(row * 128 + ((ch ^ (row & 7)) * 16));
        const size_t ga = (size_t)(block_b + row) * KDIM + j0 + ch * 8;
        cp16(sb + OFF_ARE + so, g_pre16 + ga);
        cp16(sb + OFF_AIM + so, g_pim16 + ga);
    }
    // W tile: 128 rows x 8 chunks = 1024 chunks -> 4/thread
#pragma unroll
    for (int t = 0; t < 4; ++t) {
        const int idx = tid + t * 256;
        const int row = idx >> 3;
        const int ch  = idx & 7;
        const uint32_t so = (uint32_t)(row * 128 + ((ch ^ (row & 7)) * 16));
        cp16(sb + OFF_W + so, g_W16 + (size_t)(block_k + row) * KDIM + j0 + ch * 8);
    }
}

// ---------------- phase 2: dual-GEMM + fused sigmoid ----------------
__global__ __launch_bounds__(NTHREADS, 2)
void coherence_gate_h(const float* __restrict__ pre,
                      const float* __restrict__ pim,
                      const float* __restrict__ bias,
                      float* __restrict__ out)
{
    extern __shared__ __align__(128) char smem[];
    const uint32_t sbase = smem_u32(smem);

    const int tid    = threadIdx.x;
    const int wid    = tid >> 5;
    const int lane   = tid & 31;
    const int g      = lane >> 2;
    const int tg     = lane & 3;
    const int warp_m = wid >> 2;   // 0..1 -> 32-row band
    const int warp_n = wid & 3;    // 0..3 -> 32-col band

    const int block_k = blockIdx.x * BN;
    const int block_b = blockIdx.y * BM;

    float dre[2][4][4], dim_[2][4][4];
#pragma unroll
    for (int mt = 0; mt < 2; ++mt)
#pragma unroll
        for (int nt = 0; nt < 4; ++nt)
#pragma unroll
            for (int q = 0; q < 4; ++q) { dre[mt][nt][q] = 0.f; dim_[mt][nt][q] = 0.f; }

    // ldmatrix per-thread geometry
    const int a_rl  = lane & 15;
    const int a_chi = lane >> 4;           // high bit selects 16B k-chunk
    const int w_M   = lane >> 3;           // matrix id 0..3
    const int w_r   = lane & 7;
    const int w_kc  = w_M & 1;
    const int w_nadd = (w_M >> 1) * 8;

    int arow[2], abase[2], axor[2];
#pragma unroll
    for (int mt = 0; mt < 2; ++mt) {
        arow[mt]  = warp_m * 32 + mt * 16 + a_rl;
        abase[mt] = arow[mt] * 128;
        axor[mt]  = arow[mt] & 7;
    }
    int wrow[2], wbase[2], wxor[2];
#pragma unroll
    for (int ntp = 0; ntp < 2; ++ntp) {
        wrow[ntp]  = warp_n * 32 + ntp * 16 + w_nadd + w_r;
        wbase[ntp] = wrow[ntp] * 128;
        wxor[ntp]  = wrow[ntp] & 7;
    }

    // prologue: PIPE-1 = 2 stages
    load_stage(sbase, 0, 0, block_b, block_k, tid);
    asm volatile("cp.async.commit_group;" ::: "memory");
    load_stage(sbase, 1, BK, block_b, block_k, tid);
    asm volatile("cp.async.commit_group;" ::: "memory");

    for (int s = 0; s < NS; ++s) {
        asm volatile("cp.async.wait_group 1;" ::: "memory");
        __syncthreads();

        // issue next-stage loads first (overlap with compute below)
        const int ls = s + PIPE - 1;
        if (ls < NS)
            load_stage(sbase, ls % PIPE, ls * BK, block_b, block_k, tid);
        asm volatile("cp.async.commit_group;" ::: "memory");

        const uint32_t sb = sbase + (uint32_t)(s % PIPE) * STAGE_BYTES;

#pragma unroll
        for (int ks = 0; ks < 4; ++ks) {
            uint32_t ar[2][4], ai[2][4], bw[2][4];
#pragma unroll
            for (int mt = 0; mt < 2; ++mt) {
                const uint32_t ao = (uint32_t)(abase[mt] +
                                    (((2 * ks + a_chi) ^ axor[mt]) * 16));
                ldsm4(ar[mt], sb + OFF_ARE + ao);
                ldsm4(ai[mt], sb + OFF_AIM + ao);
            }
#pragma unroll
            for (int ntp = 0; ntp < 2; ++ntp) {
                const uint32_t wo = (uint32_t)(wbase[ntp] +
                                    (((2 * ks + w_kc) ^ wxor[ntp]) * 16));
                ldsm4(bw[ntp], sb + OFF_W + wo);
            }
#pragma unroll
            for (int mt = 0; mt < 2; ++mt)
#pragma unroll
                for (int nt = 0; nt < 4; ++nt) {
                    mma16(dre[mt][nt],  ar[mt], &bw[nt >> 1][(nt & 1) * 2]);
                    mma16(dim_[mt][nt], ai[mt], &bw[nt >> 1][(nt & 1) * 2]);
                }
        }
    }

    // ---- epilogue (register-resident; undo W_SCALE) ----
#pragma unroll
    for (int mt = 0; mt < 2; ++mt) {
#pragma unroll
        for (int rr = 0; rr < 2; ++rr) {
            const int row = block_b + warp_m * 32 + mt * 16 + g + rr * 8;
            const size_t brow = (size_t)row * KDIM;
#pragma unroll
            for (int nt = 0; nt < 4; ++nt) {
                const int k = block_k + warp_n * 32 + nt * 8 + 2 * tg;
                const float2 xr = *(const float2*)&pre[brow + k];
                const float2 xi = *(const float2*)&pim[brow + k];
                const float2 bv = *(const float2*)&bias[k];
                const float ur0 = dre[mt][nt][rr * 2 + 0] * W_INV;
                const float ur1 = dre[mt][nt][rr * 2 + 1] * W_INV;
                const float ui0 = dim_[mt][nt][rr * 2 + 0] * W_INV;
                const float ui1 = dim_[mt][nt][rr * 2 + 1] * W_INV;
                float2 o;
                o.x = sigf(fmaf(xr.x, ur0, fmaf(xi.x, ui0, bv.x)));
                o.y = sigf(fmaf(xr.y, ur1, fmaf(xi.y, ui1, bv.y)));
                *(float2*)&out[brow + k] = o;
            }
        }
    }
}

extern "C" void kernel_launch(void* const* d_in, const int* in_sizes, int n_in,
                              void* d_out, int out_size)
{
    const float* pre  = (const float*)d_in[0];
    const float* pim  = (const float*)d_in[1];
    const float* Wm   = (const float*)d_in[2];
    const float* bias = (const float*)d_in[3];
    float* out = (float*)d_out;

    const int K = in_sizes[3];        // 1024
    const int B = in_sizes[0] / K;    // 8192

    const int n4_psi = (B * K) / 4;
    const int n4_w   = (K * K) / 4;
    cvt16_kernel<<<592, 256>>>((const float4*)pre, n4_psi, 1.0f, 0);
    cvt16_kernel<<<592, 256>>>((const float4*)pim, n4_psi, 1.0f, 1);
    cvt16_kernel<<<296, 256>>>((const float4*)Wm, n4_w, W_SCALE, 2);

    cudaFuncSetAttribute(coherence_gate_h,
                         cudaFuncAttributeMaxDynamicSharedMemorySize, SMEM_BYTES);
    dim3 grid(K / BN, B / BM);        // (8, 128) = 1024 CTAs
    coherence_gate_h<<<grid, NTHREADS, SMEM_BYTES>>>(pre, pim, bias, out);
}